// round 2
// baseline (speedup 1.0000x reference)
#include <cuda_runtime.h>
#include <cuda_bf16.h>
#include <math.h>

#define BB 2
#define CC 256
#define HH 64
#define WW 64
#define HW 4096
#define C8 32
#define CK 2304        // 256*9
#define CHW (CC*HW)    // 1048576

// ---------------- scratch (device globals; no allocs allowed) ----------------
__device__ __align__(16) float g_off[BB*18*HW];      // (B,18,H,W)
__device__ __align__(16) float g_S[(size_t)BB*CK*HW]; // sampled taps (B, C*9, HW)
__device__ __align__(16) float g_q[BB*C8*HW];        // deform-q, (co, p) layout
__device__ __align__(16) float g_k[BB*C8*HW];
__device__ __align__(16) float g_v[BB*CC*HW];

// ---------------- kernel 1: offset = conv3x3(x, w_off) + b_off ----------------
__global__ __launch_bounds__(256)
void off_conv_kernel(const float* __restrict__ x, const float* __restrict__ w,
                     const float* __restrict__ bias) {
    __shared__ float ws[CK];
    int o = blockIdx.y;            // 0..17
    int b = blockIdx.z;
    int p = blockIdx.x * 256 + threadIdx.x;   // 0..4095
    for (int i = threadIdx.x; i < CK; i += 256) ws[i] = w[o*CK + i];
    __syncthreads();
    int yy = p >> 6, xx = p & 63;
    const float* xb = x + (size_t)b*CHW;
    float acc = bias[o];
    for (int c = 0; c < CC; c++) {
        const float* xc = xb + c*HW;
        const float* wr = ws + c*9;
        #pragma unroll
        for (int t = 0; t < 9; t++) {
            int y2 = yy + (t/3) - 1;
            int x2 = xx + (t%3) - 1;
            if ((unsigned)y2 < 64u && (unsigned)x2 < 64u)
                acc += xc[y2*64 + x2] * wr[t];
        }
    }
    g_off[((size_t)b*18 + o)*HW + p] = acc;
}

// ---------------- kernel 2: bilinear sampling S[b, c*9+t, p] ----------------
__global__ __launch_bounds__(256)
void sample_kernel(const float* __restrict__ x) {
    int tid = blockIdx.x * 256 + threadIdx.x;   // B*9*HW = 73728 threads
    int p = tid & (HW - 1);
    int t = (tid >> 12) % 9;
    int b = tid / (9*HW);
    int yy = p >> 6, xx = p & 63;
    float dy = g_off[((size_t)b*18 + 2*t    )*HW + p];
    float dx = g_off[((size_t)b*18 + 2*t + 1)*HW + p];
    float py = (float)yy + (float)(t/3 - 1) + dy;
    float px = (float)xx + (float)(t%3 - 1) + dx;
    float y0f = floorf(py), x0f = floorf(px);
    float wy = py - y0f, wx = px - x0f;
    int y0 = (int)y0f, x0 = (int)x0f;
    int y1 = y0 + 1, x1 = x0 + 1;
    bool vy0 = (y0 >= 0) && (y0 < 64), vy1 = (y1 >= 0) && (y1 < 64);
    bool vx0 = (x0 >= 0) && (x0 < 64), vx1 = (x1 >= 0) && (x1 < 64);
    float w00 = (1.f-wy)*(1.f-wx) * (float)(vy0 && vx0);
    float w01 = (1.f-wy)*wx       * (float)(vy0 && vx1);
    float w10 = wy*(1.f-wx)       * (float)(vy1 && vx0);
    float w11 = wy*wx             * (float)(vy1 && vx1);
    int cy0 = min(max(y0,0),63), cy1 = min(max(y1,0),63);
    int cx0 = min(max(x0,0),63), cx1 = min(max(x1,0),63);
    int i00 = cy0*64+cx0, i01 = cy0*64+cx1, i10 = cy1*64+cx0, i11 = cy1*64+cx1;
    const float* xb = x + (size_t)b*CHW;
    float* Sb = g_S + (size_t)b*CK*HW;
    for (int c = 0; c < CC; c++) {
        const float* xc = xb + c*HW;
        float v = w00*xc[i00] + w01*xc[i01] + w10*xc[i10] + w11*xc[i11];
        Sb[(size_t)(c*9 + t)*HW + p] = v;
    }
}

// ---------------- kernel 3: D(M x 4096) = W(M x 2304) @ S + bias ----------------
// sel: 0 -> g_q, 1 -> g_k, 2 -> g_v
__global__ __launch_bounds__(256)
void gemm_kernel(const float* __restrict__ Wm, const float* __restrict__ bias,
                 int M, int sel) {
    __shared__ float As[16][65];
    __shared__ float Bs[16][64];
    int b  = blockIdx.z;
    int m0 = blockIdx.y * 64;
    int p0 = blockIdx.x * 64;
    const float* Sb = g_S + (size_t)b*CK*HW;
    float* D = (sel == 0) ? g_q : (sel == 1) ? g_k : g_v;
    float* Db = D + (size_t)b*M*HW;
    int t = threadIdx.x;
    int tr = t >> 4, tc = t & 15;
    float acc[4][4] = {};
    for (int k0 = 0; k0 < CK; k0 += 16) {
        {   // load 16x64 W-tile, stored transposed As[kk][mm]
            int kk = t & 15; int mmbase = t >> 4;
            #pragma unroll
            for (int i = 0; i < 4; i++) {
                int mm = mmbase + i*16;
                int m  = m0 + mm;
                As[kk][mm] = (m < M) ? Wm[(size_t)m*CK + k0 + kk] : 0.f;
            }
        }
        {   // load 16x64 S-tile
            int pp = t & 63; int kkbase = t >> 6;
            #pragma unroll
            for (int i = 0; i < 4; i++) {
                int kk = kkbase + i*4;
                Bs[kk][pp] = Sb[(size_t)(k0 + kk)*HW + p0 + pp];
            }
        }
        __syncthreads();
        #pragma unroll
        for (int kk = 0; kk < 16; kk++) {
            float a[4];
            #pragma unroll
            for (int i = 0; i < 4; i++) a[i] = As[kk][tr*4 + i];
            float4 bv = *(const float4*)&Bs[kk][tc*4];
            float bb[4] = {bv.x, bv.y, bv.z, bv.w};
            #pragma unroll
            for (int i = 0; i < 4; i++)
                #pragma unroll
                for (int j = 0; j < 4; j++) acc[i][j] += a[i]*bb[j];
        }
        __syncthreads();
    }
    #pragma unroll
    for (int i = 0; i < 4; i++) {
        int m = m0 + tr*4 + i;
        if (m < M) {
            float bsv = bias[m];
            #pragma unroll
            for (int j = 0; j < 4; j++)
                Db[(size_t)m*HW + p0 + tc*4 + j] = acc[i][j] + bsv;
        }
    }
}

// ---------------- kernel 4: flash attention + fused epilogue ----------------
// Q row-major (4096,32) == g_q flat; K same; V row-major (4096,256) == g_v flat.
// out[b, q*256+c] = gamma * (softmax(QK^T) @ V)[q][c] + x[b, q*256+c]
#define SM_QS 0
#define SM_KS (64*33)
#define SM_PS (2*64*33)
#define SM_VS (2*64*33 + 64*65)
#define SM_RM (2*64*33 + 64*65 + 64*256)
#define SM_RL (SM_RM + 64)
#define SM_RA (SM_RL + 64)
#define SM_FLOATS (SM_RA + 64)          // 24960 floats = 99840 bytes

__global__ __launch_bounds__(256)
void attn_kernel(const float* __restrict__ x, const float* __restrict__ gamma,
                 float* __restrict__ out) {
    extern __shared__ float sm[];
    float* Qs = sm + SM_QS;
    float* Ks = sm + SM_KS;
    float* Ps = sm + SM_PS;
    float* Vs = sm + SM_VS;
    float* rowm = sm + SM_RM;
    float* rowl = sm + SM_RL;
    float* rowa = sm + SM_RA;

    int b  = blockIdx.y;
    int q0 = blockIdx.x * 64;
    int t  = threadIdx.x;
    const float* Qb = g_q + (size_t)b*C8*HW;
    const float* Kb = g_k + (size_t)b*C8*HW;
    const float* Vb = g_v + (size_t)b*CHW;

    for (int i = t; i < 64*32; i += 256) {
        int r = i >> 5, c = i & 31;
        Qs[r*33 + c] = Qb[(size_t)(q0 + r)*32 + c];
    }
    if (t < 64) { rowm[t] = -1e30f; rowl[t] = 0.f; }
    __syncthreads();

    int tr = t >> 4, tc = t & 15;
    int r0 = tr * 4, c0 = tc * 16;
    float O[4][16];
    #pragma unroll
    for (int i = 0; i < 4; i++)
        #pragma unroll
        for (int j = 0; j < 16; j++) O[i][j] = 0.f;

    for (int kt = 0; kt < 64; kt++) {
        for (int i = t; i < 64*32; i += 256) {
            int r = i >> 5, c = i & 31;
            Ks[r*33 + c] = Kb[(size_t)(kt*64 + r)*32 + c];
        }
        {
            const float4* Vg  = (const float4*)(Vb + (size_t)kt*64*256);
            float4* Vs4 = (float4*)Vs;
            for (int i = t; i < 4096; i += 256) Vs4[i] = Vg[i];
        }
        __syncthreads();
        // logits S[64][64]: each thread 4x4
        {
            float acc[4][4] = {};
            #pragma unroll
            for (int kk = 0; kk < 32; kk++) {
                float a[4], bv[4];
                #pragma unroll
                for (int i = 0; i < 4; i++) a[i]  = Qs[(r0 + i)*33 + kk];
                #pragma unroll
                for (int j = 0; j < 4; j++) bv[j] = Ks[(tc*4 + j)*33 + kk];
                #pragma unroll
                for (int i = 0; i < 4; i++)
                    #pragma unroll
                    for (int j = 0; j < 4; j++) acc[i][j] += a[i]*bv[j];
            }
            #pragma unroll
            for (int i = 0; i < 4; i++)
                #pragma unroll
                for (int j = 0; j < 4; j++)
                    Ps[(r0 + i)*65 + tc*4 + j] = acc[i][j];
        }
        __syncthreads();
        // online softmax per row (64 rows by 64 threads)
        if (t < 64) {
            int r = t;
            float m_old = rowm[r];
            float mx = m_old;
            #pragma unroll 8
            for (int j = 0; j < 64; j++) mx = fmaxf(mx, Ps[r*65 + j]);
            float s = 0.f;
            #pragma unroll 8
            for (int j = 0; j < 64; j++) {
                float e = __expf(Ps[r*65 + j] - mx);
                Ps[r*65 + j] = e;
                s += e;
            }
            float alpha = __expf(m_old - mx);
            rowl[r] = rowl[r]*alpha + s;
            rowm[r] = mx;
            rowa[r] = alpha;
        }
        __syncthreads();
        // O = O*alpha + P @ V  (thread: 4 rows x 16 cols)
        {
            float al[4];
            #pragma unroll
            for (int i = 0; i < 4; i++) al[i] = rowa[r0 + i];
            #pragma unroll
            for (int i = 0; i < 4; i++)
                #pragma unroll
                for (int j = 0; j < 16; j++) O[i][j] *= al[i];
            for (int j = 0; j < 64; j++) {
                float p[4];
                #pragma unroll
                for (int i = 0; i < 4; i++) p[i] = Ps[(r0 + i)*65 + j];
                const float4* vr = (const float4*)&Vs[j*256 + c0];
                float4 v0 = vr[0], v1 = vr[1], v2 = vr[2], v3 = vr[3];
                float vv[16] = {v0.x,v0.y,v0.z,v0.w, v1.x,v1.y,v1.z,v1.w,
                                v2.x,v2.y,v2.z,v2.w, v3.x,v3.y,v3.z,v3.w};
                #pragma unroll
                for (int i = 0; i < 4; i++)
                    #pragma unroll
                    for (int jj = 0; jj < 16; jj++) O[i][jj] += p[i]*vv[jj];
            }
        }
        __syncthreads();
    }
    // epilogue: divide by l, gamma*out + x  (flat reshape semantics)
    float g = gamma[0];
    #pragma unroll
    for (int i = 0; i < 4; i++) {
        int qi = q0 + r0 + i;
        float inv = 1.f / rowl[r0 + i];
        #pragma unroll
        for (int jj = 0; jj < 16; jj++) {
            size_t n = (size_t)b*CHW + (size_t)qi*256 + c0 + jj;
            out[n] = g * (O[i][jj]*inv) + x[n];
        }
    }
}

// ---------------- launch ----------------
extern "C" void kernel_launch(void* const* d_in, const int* in_sizes, int n_in,
                              void* d_out, int out_size) {
    const float* x     = (const float*)d_in[0];
    const float* w_off = (const float*)d_in[1];
    const float* b_off = (const float*)d_in[2];
    const float* wq    = (const float*)d_in[3];
    const float* bq    = (const float*)d_in[4];
    const float* wk    = (const float*)d_in[5];
    const float* bk    = (const float*)d_in[6];
    const float* wv    = (const float*)d_in[7];
    const float* bv    = (const float*)d_in[8];
    const float* gamma = (const float*)d_in[9];
    float* out = (float*)d_out;

    off_conv_kernel<<<dim3(16, 18, BB), 256>>>(x, w_off, b_off);
    sample_kernel<<<(BB*9*HW)/256, 256>>>(x);
    gemm_kernel<<<dim3(64, 1, BB), 256>>>(wq, bq, C8, 0);
    gemm_kernel<<<dim3(64, 1, BB), 256>>>(wk, bk, C8, 1);
    gemm_kernel<<<dim3(64, 4, BB), 256>>>(wv, bv, CC, 2);

    cudaFuncSetAttribute(attn_kernel, cudaFuncAttributeMaxDynamicSharedMemorySize,
                         SM_FLOATS * (int)sizeof(float));
    attn_kernel<<<dim3(64, BB), 256, SM_FLOATS * sizeof(float)>>>(x, gamma, out);
}

// round 6
// speedup vs baseline: 2.4987x; 2.4987x over previous
#include <cuda_runtime.h>
#include <cuda_bf16.h>
#include <cuda_fp16.h>
#include <math.h>
#include <stdint.h>

#define BB 2
#define CC 256
#define HW 4096
#define C8 32
#define CK 2304        // 256*9
#define CHW (CC*HW)
#define VT_ST 72       // padded key-row stride in g_vt / Vs

// ---------------- scratch (device globals) ----------------
__device__ __align__(16) float g_off[BB*18*HW];
__device__ __align__(16) __nv_bfloat16 g_Sh[(size_t)BB*CK*HW];   // sampled taps hi (b, ck, p)
__device__ __align__(16) __nv_bfloat16 g_Sl[(size_t)BB*CK*HW];   // lo
// q/k stored CHANNEL-MAJOR flat [n][p] (raw-reshape semantics), hi/lo bf16
__device__ __align__(16) __nv_bfloat16 g_qh[BB*C8*HW], g_ql[BB*C8*HW];
__device__ __align__(16) __nv_bfloat16 g_kh[BB*C8*HW], g_kl[BB*C8*HW];
// v stored pre-transposed per 64-key tile: g_vt[b][kt][ch][klo], fp16, klo stride VT_ST
__device__ __align__(16) __half g_vt[(size_t)BB*64*256*VT_ST];

// ---------------- helpers ----------------
__device__ __forceinline__ void mma_bf16(float c[4], const uint32_t a[4], const uint32_t b[2]) {
    asm volatile(
        "mma.sync.aligned.m16n8k16.row.col.f32.bf16.bf16.f32 "
        "{%0,%1,%2,%3}, {%4,%5,%6,%7}, {%8,%9}, {%0,%1,%2,%3};\n"
        : "+f"(c[0]), "+f"(c[1]), "+f"(c[2]), "+f"(c[3])
        : "r"(a[0]), "r"(a[1]), "r"(a[2]), "r"(a[3]), "r"(b[0]), "r"(b[1]));
}
__device__ __forceinline__ void mma_f16(float c[4], const uint32_t a[4], const uint32_t b[2]) {
    asm volatile(
        "mma.sync.aligned.m16n8k16.row.col.f32.f16.f16.f32 "
        "{%0,%1,%2,%3}, {%4,%5,%6,%7}, {%8,%9}, {%0,%1,%2,%3};\n"
        : "+f"(c[0]), "+f"(c[1]), "+f"(c[2]), "+f"(c[3])
        : "r"(a[0]), "r"(a[1]), "r"(a[2]), "r"(a[3]), "r"(b[0]), "r"(b[1]));
}
__device__ __forceinline__ void split_bf16(float v, __nv_bfloat16& h, __nv_bfloat16& l) {
    h = __float2bfloat16(v);
    l = __float2bfloat16(v - __bfloat162float(h));
}

// ---------------- kernel 1: offset conv ----------------
__global__ __launch_bounds__(256)
void off_conv_kernel(const float* __restrict__ x, const float* __restrict__ w,
                     const float* __restrict__ bias) {
    __shared__ float ws[CK];
    int o = blockIdx.y;
    int b = blockIdx.z;
    int p = blockIdx.x * 256 + threadIdx.x;
    for (int i = threadIdx.x; i < CK; i += 256) ws[i] = w[o*CK + i];
    __syncthreads();
    int yy = p >> 6, xx = p & 63;
    const float* xb = x + (size_t)b*CHW;
    float acc = bias[o];
    for (int c = 0; c < CC; c++) {
        const float* xc = xb + c*HW;
        const float* wr = ws + c*9;
        #pragma unroll
        for (int t = 0; t < 9; t++) {
            int y2 = yy + (t/3) - 1;
            int x2 = xx + (t%3) - 1;
            if ((unsigned)y2 < 64u && (unsigned)x2 < 64u)
                acc += xc[y2*64 + x2] * wr[t];
        }
    }
    g_off[((size_t)b*18 + o)*HW + p] = acc;
}

// ---------------- kernel 2: bilinear sampling -> S hi/lo ----------------
__global__ __launch_bounds__(256)
void sample_kernel(const float* __restrict__ x) {
    int tid = blockIdx.x * 256 + threadIdx.x;
    int p = tid & (HW - 1);
    int t = (tid >> 12) % 9;
    int b = tid / (9*HW);
    int yy = p >> 6, xx = p & 63;
    float dy = g_off[((size_t)b*18 + 2*t    )*HW + p];
    float dx = g_off[((size_t)b*18 + 2*t + 1)*HW + p];
    float py = (float)yy + (float)(t/3 - 1) + dy;
    float px = (float)xx + (float)(t%3 - 1) + dx;
    float y0f = floorf(py), x0f = floorf(px);
    float wy = py - y0f, wx = px - x0f;
    int y0 = (int)y0f, x0 = (int)x0f;
    int y1 = y0 + 1, x1 = x0 + 1;
    bool vy0 = (y0 >= 0) && (y0 < 64), vy1 = (y1 >= 0) && (y1 < 64);
    bool vx0 = (x0 >= 0) && (x0 < 64), vx1 = (x1 >= 0) && (x1 < 64);
    float w00 = (1.f-wy)*(1.f-wx) * (float)(vy0 && vx0);
    float w01 = (1.f-wy)*wx       * (float)(vy0 && vx1);
    float w10 = wy*(1.f-wx)       * (float)(vy1 && vx0);
    float w11 = wy*wx             * (float)(vy1 && vx1);
    int cy0 = min(max(y0,0),63), cy1 = min(max(y1,0),63);
    int cx0 = min(max(x0,0),63), cx1 = min(max(x1,0),63);
    int i00 = cy0*64+cx0, i01 = cy0*64+cx1, i10 = cy1*64+cx0, i11 = cy1*64+cx1;
    const float* xb = x + (size_t)b*CHW;
    size_t base = (size_t)b*CK*HW;
    for (int c = 0; c < CC; c++) {
        const float* xc = xb + c*HW;
        float v = w00*xc[i00] + w01*xc[i01] + w10*xc[i10] + w11*xc[i11];
        __nv_bfloat16 h, l;
        split_bf16(v, h, l);
        size_t idx = base + (size_t)(c*9 + t)*HW + p;
        g_Sh[idx] = h;
        g_Sl[idx] = l;
    }
}

// ---------------- kernel 3: q,k GEMM, D[n][p] channel-major, 3-pass split ----------------
#define SM_ST 34
__global__ __launch_bounds__(256)
void qk_gemm_kernel(const float* __restrict__ Wq, const float* __restrict__ bq,
                    const float* __restrict__ Wk, const float* __restrict__ bk) {
    __shared__ __nv_bfloat16 Sh[64][SM_ST], Sl[64][SM_ST];
    __shared__ __nv_bfloat16 Whs[64][SM_ST], Wls[64][SM_ST];
    int b  = blockIdx.y;
    int p0 = blockIdx.x * 64;
    int t = threadIdx.x, lane = t & 31, w = t >> 5;
    int g = lane >> 2, tq = lane & 3;
    int wn = w >> 1, wp = w & 1;       // warp: 16 n-rows x 32 p-cols
    int n0 = 16*wn, pc0 = 32*wp;
    size_t sbase = (size_t)b*CK*HW;

    float acc[4][4];
    #pragma unroll
    for (int i = 0; i < 4; i++)
        #pragma unroll
        for (int j = 0; j < 4; j++) acc[i][j] = 0.f;

    for (int k0 = 0; k0 < CK; k0 += 32) {
        for (int i = t; i < 1024; i += 256) {       // S^T: 32k x 64p -> [p][k]
            int kk = i >> 5, pl = (i & 31) * 2;
            size_t gi = sbase + (size_t)(k0 + kk)*HW + p0 + pl;
            __nv_bfloat162 vh = *(const __nv_bfloat162*)(g_Sh + gi);
            __nv_bfloat162 vl = *(const __nv_bfloat162*)(g_Sl + gi);
            Sh[pl][kk] = vh.x; Sh[pl+1][kk] = vh.y;
            Sl[pl][kk] = vl.x; Sl[pl+1][kk] = vl.y;
        }
        for (int i = t; i < 2048; i += 256) {       // W: 64n x 32k, hi/lo
            int m = i >> 5, kk = i & 31;
            const float* Wsrc = (m < 32) ? (Wq + (size_t)m*CK) : (Wk + (size_t)(m-32)*CK);
            float v = Wsrc[k0 + kk];
            split_bf16(v, Whs[m][kk], Wls[m][kk]);
        }
        __syncthreads();

        uint32_t Ah[2][4], Al[2][4];
        int ar = n0 + g;
        #pragma unroll
        for (int ks = 0; ks < 2; ks++) {
            int kc = ks*16 + 2*tq;
            Ah[ks][0] = *(const uint32_t*)&Whs[ar    ][kc  ];
            Ah[ks][1] = *(const uint32_t*)&Whs[ar + 8][kc  ];
            Ah[ks][2] = *(const uint32_t*)&Whs[ar    ][kc+8];
            Ah[ks][3] = *(const uint32_t*)&Whs[ar + 8][kc+8];
            Al[ks][0] = *(const uint32_t*)&Wls[ar    ][kc  ];
            Al[ks][1] = *(const uint32_t*)&Wls[ar + 8][kc  ];
            Al[ks][2] = *(const uint32_t*)&Wls[ar    ][kc+8];
            Al[ks][3] = *(const uint32_t*)&Wls[ar + 8][kc+8];
        }
        #pragma unroll
        for (int nf = 0; nf < 4; nf++) {
            int pcol = pc0 + 8*nf + g;
            #pragma unroll
            for (int ks = 0; ks < 2; ks++) {
                int kc = ks*16 + 2*tq;
                uint32_t Bh[2], Bl[2];
                Bh[0] = *(const uint32_t*)&Sh[pcol][kc  ];
                Bh[1] = *(const uint32_t*)&Sh[pcol][kc+8];
                Bl[0] = *(const uint32_t*)&Sl[pcol][kc  ];
                Bl[1] = *(const uint32_t*)&Sl[pcol][kc+8];
                mma_bf16(acc[nf], Ah[ks], Bh);
                mma_bf16(acc[nf], Ah[ks], Bl);
                mma_bf16(acc[nf], Al[ks], Bh);
            }
        }
        __syncthreads();
    }
    // epilogue: rows n (channel), cols p; channel-major store, hi/lo
    #pragma unroll
    for (int half = 0; half < 2; half++) {
        int n = n0 + g + 8*half;
        float bz = (n < 32) ? bq[n] : bk[n - 32];
        __nv_bfloat16* dh = (n < 32) ? (g_qh + ((size_t)b*C8 + n)*HW)
                                     : (g_kh + ((size_t)b*C8 + n - 32)*HW);
        __nv_bfloat16* dl = (n < 32) ? (g_ql + ((size_t)b*C8 + n)*HW)
                                     : (g_kl + ((size_t)b*C8 + n - 32)*HW);
        #pragma unroll
        for (int nf = 0; nf < 4; nf++) {
            int p = p0 + pc0 + 8*nf + 2*tq;
            float v0 = acc[nf][2*half]   + bz;
            float v1 = acc[nf][2*half+1] + bz;
            __nv_bfloat16 h0,l0,h1,l1;
            split_bf16(v0, h0, l0); split_bf16(v1, h1, l1);
            *(__nv_bfloat162*)(dh + p) = __nv_bfloat162{h0, h1};
            *(__nv_bfloat162*)(dl + p) = __nv_bfloat162{l0, l1};
        }
    }
}

// ---------------- kernel 4: v GEMM (3-pass split), out pre-transposed fp16 tiles ----------------
__global__ __launch_bounds__(256)
void v_gemm_kernel(const float* __restrict__ Wv, const float* __restrict__ bv) {
    __shared__ __nv_bfloat16 Ssh[128][SM_ST], Ssl[128][SM_ST];
    __shared__ __nv_bfloat16 Wsh[64][SM_ST], Wsl[64][SM_ST];
    int b  = blockIdx.z;
    int m0 = blockIdx.x * 64;      // x = channel tile (fast) so p-sharing blocks co-run
    int p0 = blockIdx.y * 128;
    int t = threadIdx.x, lane = t & 31, w = t >> 5;
    int g = lane >> 2, tq = lane & 3;
    int wm = w >> 2, wn = w & 3;       // warp: 32 m-rows x 32 p-cols
    size_t sbase = (size_t)b*CK*HW;

    float acc[2][4][4];
    #pragma unroll
    for (int a = 0; a < 2; a++)
        #pragma unroll
        for (int i = 0; i < 4; i++)
            #pragma unroll
            for (int j = 0; j < 4; j++) acc[a][i][j] = 0.f;

    for (int k0 = 0; k0 < CK; k0 += 32) {
        for (int i = t; i < 2048; i += 256) {     // S^T: 32k x 128p, hi+lo
            int kk = i >> 6, pl = (i & 63) * 2;
            size_t gi = sbase + (size_t)(k0 + kk)*HW + p0 + pl;
            __nv_bfloat162 vh = *(const __nv_bfloat162*)(g_Sh + gi);
            __nv_bfloat162 vl = *(const __nv_bfloat162*)(g_Sl + gi);
            Ssh[pl][kk] = vh.x; Ssh[pl+1][kk] = vh.y;
            Ssl[pl][kk] = vl.x; Ssl[pl+1][kk] = vl.y;
        }
        for (int i = t; i < 2048; i += 256) {     // W: 64m x 32k hi/lo
            int m = i >> 5, kk = i & 31;
            float v = Wv[(size_t)(m0 + m)*CK + k0 + kk];
            split_bf16(v, Wsh[m][kk], Wsl[m][kk]);
        }
        __syncthreads();

        #pragma unroll
        for (int ks = 0; ks < 2; ks++) {
            int kc = ks*16 + 2*tq;
            uint32_t Ah[2][4], Al[2][4];
            #pragma unroll
            for (int mf = 0; mf < 2; mf++) {
                int r = 32*wm + 16*mf + g;
                Ah[mf][0] = *(const uint32_t*)&Wsh[r    ][kc  ];
                Ah[mf][1] = *(const uint32_t*)&Wsh[r + 8][kc  ];
                Ah[mf][2] = *(const uint32_t*)&Wsh[r    ][kc+8];
                Ah[mf][3] = *(const uint32_t*)&Wsh[r + 8][kc+8];
                Al[mf][0] = *(const uint32_t*)&Wsl[r    ][kc  ];
                Al[mf][1] = *(const uint32_t*)&Wsl[r + 8][kc  ];
                Al[mf][2] = *(const uint32_t*)&Wsl[r    ][kc+8];
                Al[mf][3] = *(const uint32_t*)&Wsl[r + 8][kc+8];
            }
            #pragma unroll
            for (int nf = 0; nf < 4; nf++) {
                int n = 32*wn + 8*nf + g;
                uint32_t Bh[2], Bl[2];
                Bh[0] = *(const uint32_t*)&Ssh[n][kc  ];
                Bh[1] = *(const uint32_t*)&Ssh[n][kc+8];
                Bl[0] = *(const uint32_t*)&Ssl[n][kc  ];
                Bl[1] = *(const uint32_t*)&Ssl[n][kc+8];
                mma_bf16(acc[0][nf], Ah[0], Bh);
                mma_bf16(acc[0][nf], Ah[0], Bl);
                mma_bf16(acc[0][nf], Al[0], Bh);
                mma_bf16(acc[1][nf], Ah[1], Bh);
                mma_bf16(acc[1][nf], Ah[1], Bl);
                mma_bf16(acc[1][nf], Al[1], Bh);
            }
        }
        __syncthreads();
    }
    // epilogue: element (m, p) is raw-flat j = m*4096+p -> V'[key][ch],
    // key = j>>8 = m*16 + (p0>>8) (p never crosses a 256 boundary in-block), ch = p&255.
    // store at g_vt[b][key>>6][ch][key&63], fp16, scattered scalar.
    int phi = p0 >> 8;
    #pragma unroll
    for (int mf = 0; mf < 2; mf++) {
        #pragma unroll
        for (int half = 0; half < 2; half++) {
            int m = m0 + 32*wm + 16*mf + g + 8*half;
            float bz = bv[m];
            int key = m*16 + phi;
            size_t tbase = ((size_t)b*64 + (key >> 6))*(256*VT_ST) + (key & 63);
            #pragma unroll
            for (int nf = 0; nf < 4; nf++) {
                int p = p0 + 32*wn + 8*nf + 2*tq;
                int ch0 = p & 255;
                float v0 = acc[mf][nf][2*half]   + bz;
                float v1 = acc[mf][nf][2*half+1] + bz;
                g_vt[tbase + (size_t)ch0*VT_ST]     = __float2half(v0);
                g_vt[tbase + (size_t)(ch0+1)*VT_ST] = __float2half(v1);
            }
        }
    }
}

// ---------------- kernel 5: flash attention + fused epilogue ----------------
// smem: Ps fp32[64*72] | Pb fp16[64*72] | Vs fp16[256*72] | rowm/rowl/rowa[64]
#define SMEM_BYTES (64*VT_ST*4 + 64*VT_ST*2 + 256*VT_ST*2 + 3*64*4)

__global__ __launch_bounds__(256)
void attn_kernel(const float* __restrict__ x, const float* __restrict__ gamma,
                 float* __restrict__ out) {
    extern __shared__ char smem_raw[];
    float* Ps = (float*)smem_raw;
    __half* Pb = (__half*)(Ps + 64*VT_ST);
    __half* Vs = Pb + 64*VT_ST;
    float* rowm = (float*)(Vs + 256*VT_ST);
    float* rowl = rowm + 64;
    float* rowa = rowl + 64;

    int b  = blockIdx.y;
    int q0 = blockIdx.x * 64;
    int t = threadIdx.x, lane = t & 31, w = t >> 5;
    int g = lane >> 2, tq = lane & 3;
    int wq = w >> 1, wh = w & 1;

    const __nv_bfloat16* Qh = g_qh + (size_t)b*C8*HW;   // flat raw-reshape row-major (4096,32)
    const __nv_bfloat16* Ql = g_ql + (size_t)b*C8*HW;
    const __nv_bfloat16* Kh = g_kh + (size_t)b*C8*HW;
    const __nv_bfloat16* Kl = g_kl + (size_t)b*C8*HW;
    const __half* Vt = g_vt + (size_t)b*64*256*VT_ST;

    uint32_t qAh[2][4], qAl[2][4];
    {
        int qrow = q0 + 16*wq + g;
        #pragma unroll
        for (int ks = 0; ks < 2; ks++) {
            int kc = ks*16 + 2*tq;
            qAh[ks][0] = *(const uint32_t*)(Qh + (size_t)qrow*32 + kc);
            qAh[ks][1] = *(const uint32_t*)(Qh + (size_t)(qrow+8)*32 + kc);
            qAh[ks][2] = *(const uint32_t*)(Qh + (size_t)qrow*32 + kc + 8);
            qAh[ks][3] = *(const uint32_t*)(Qh + (size_t)(qrow+8)*32 + kc + 8);
            qAl[ks][0] = *(const uint32_t*)(Ql + (size_t)qrow*32 + kc);
            qAl[ks][1] = *(const uint32_t*)(Ql + (size_t)(qrow+8)*32 + kc);
            qAl[ks][2] = *(const uint32_t*)(Ql + (size_t)qrow*32 + kc + 8);
            qAl[ks][3] = *(const uint32_t*)(Ql + (size_t)(qrow+8)*32 + kc + 8);
        }
    }
    if (t < 64) { rowm[t] = -1e30f; rowl[t] = 0.f; }

    float O[16][4];
    #pragma unroll
    for (int i = 0; i < 16; i++)
        #pragma unroll
        for (int j = 0; j < 4; j++) O[i][j] = 0.f;
    __syncthreads();

    for (int kt = 0; kt < 64; kt++) {
        // stage V' tile transposed [ch][key] — contiguous copy from g_vt
        {
            const __half* src = Vt + (size_t)kt*256*VT_ST;
            for (int i = t; i < 2048; i += 256) {
                int c = i >> 3, seg = i & 7;
                uint4 vv = *(const uint4*)(src + c*VT_ST + seg*8);
                *(uint4*)(Vs + c*VT_ST + seg*8) = vv;
            }
        }
        // QK logits (3-pass split)
        float qacc[4][4];
        #pragma unroll
        for (int i = 0; i < 4; i++)
            #pragma unroll
            for (int j = 0; j < 4; j++) qacc[i][j] = 0.f;
        #pragma unroll
        for (int nf = 0; nf < 4; nf++) {
            int key = kt*64 + 32*wh + 8*nf + g;
            #pragma unroll
            for (int ks = 0; ks < 2; ks++) {
                int kc = ks*16 + 2*tq;
                uint32_t Bh[2], Bl[2];
                Bh[0] = *(const uint32_t*)(Kh + (size_t)key*32 + kc);
                Bh[1] = *(const uint32_t*)(Kh + (size_t)key*32 + kc + 8);
                Bl[0] = *(const uint32_t*)(Kl + (size_t)key*32 + kc);
                Bl[1] = *(const uint32_t*)(Kl + (size_t)key*32 + kc + 8);
                mma_bf16(qacc[nf], qAh[ks], Bh);
                mma_bf16(qacc[nf], qAh[ks], Bl);
                mma_bf16(qacc[nf], qAl[ks], Bh);
            }
        }
        {
            int pr = 16*wq + g;
            #pragma unroll
            for (int nf = 0; nf < 4; nf++) {
                int pc = 32*wh + 8*nf + 2*tq;
                Ps[pr*VT_ST + pc]       = qacc[nf][0];
                Ps[pr*VT_ST + pc + 1]   = qacc[nf][1];
                Ps[(pr+8)*VT_ST + pc]   = qacc[nf][2];
                Ps[(pr+8)*VT_ST + pc+1] = qacc[nf][3];
            }
        }
        __syncthreads();
        // online softmax: 4 threads/row
        {
            int r = t >> 2, sg = t & 3;
            const float* pr = Ps + r*VT_ST + sg*16;
            float mx = -1e30f;
            #pragma unroll
            for (int j = 0; j < 16; j++) mx = fmaxf(mx, pr[j]);
            mx = fmaxf(mx, __shfl_xor_sync(0xffffffffu, mx, 1));
            mx = fmaxf(mx, __shfl_xor_sync(0xffffffffu, mx, 2));
            float mold = rowm[r];
            float mnew = fmaxf(mold, mx);
            float s = 0.f;
            __half* pb = Pb + r*VT_ST + sg*16;
            #pragma unroll
            for (int j = 0; j < 16; j++) {
                float e = __expf(pr[j] - mnew);
                s += e;
                pb[j] = __float2half(e);
            }
            s += __shfl_xor_sync(0xffffffffu, s, 1);
            s += __shfl_xor_sync(0xffffffffu, s, 2);
            if (sg == 0) {
                float alpha = __expf(mold - mnew);
                rowm[r] = mnew;
                rowl[r] = rowl[r]*alpha + s;
                rowa[r] = alpha;
            }
        }
        __syncthreads();
        // PV: O = O*alpha + P @ V'  (fp16 single pass)
        {
            float al0 = rowa[16*wq + g];
            float al1 = rowa[16*wq + g + 8];
            #pragma unroll
            for (int nf = 0; nf < 16; nf++) {
                O[nf][0] *= al0; O[nf][1] *= al0;
                O[nf][2] *= al1; O[nf][3] *= al1;
            }
            int arow = 16*wq + g;
            #pragma unroll
            for (int ks = 0; ks < 4; ks++) {
                int kc = ks*16 + 2*tq;
                uint32_t pA[4];
                pA[0] = *(const uint32_t*)(Pb + arow*VT_ST + kc);
                pA[1] = *(const uint32_t*)(Pb + (arow+8)*VT_ST + kc);
                pA[2] = *(const uint32_t*)(Pb + arow*VT_ST + kc + 8);
                pA[3] = *(const uint32_t*)(Pb + (arow+8)*VT_ST + kc + 8);
                #pragma unroll
                for (int nf = 0; nf < 16; nf++) {
                    int ch = 128*wh + 8*nf + g;
                    uint32_t Bv[2];
                    Bv[0] = *(const uint32_t*)(Vs + ch*VT_ST + kc);
                    Bv[1] = *(const uint32_t*)(Vs + ch*VT_ST + kc + 8);
                    mma_f16(O[nf], pA, Bv);
                }
            }
        }
        __syncthreads();
    }
    // epilogue: gamma * O/l + x  (raw-reshape flat indexing)
    {
        float gm = gamma[0];
        int row0 = q0 + 16*wq + g;
        float inv0 = 1.f / rowl[16*wq + g];
        float inv1 = 1.f / rowl[16*wq + g + 8];
        #pragma unroll
        for (int nf = 0; nf < 16; nf++) {
            int ch = 128*wh + 8*nf + 2*tq;
            size_t i0 = (size_t)b*CHW + (size_t)row0*256 + ch;
            size_t i1 = (size_t)b*CHW + (size_t)(row0+8)*256 + ch;
            out[i0]   = gm*O[nf][0]*inv0 + x[i0];
            out[i0+1] = gm*O[nf][1]*inv0 + x[i0+1];
            out[i1]   = gm*O[nf][2]*inv1 + x[i1];
            out[i1+1] = gm*O[nf][3]*inv1 + x[i1+1];
        }
    }
}

// ---------------- launch ----------------
extern "C" void kernel_launch(void* const* d_in, const int* in_sizes, int n_in,
                              void* d_out, int out_size) {
    const float* x     = (const float*)d_in[0];
    const float* w_off = (const float*)d_in[1];
    const float* b_off = (const float*)d_in[2];
    const float* wq    = (const float*)d_in[3];
    const float* bq    = (const float*)d_in[4];
    const float* wk    = (const float*)d_in[5];
    const float* bk    = (const float*)d_in[6];
    const float* wv    = (const float*)d_in[7];
    const float* bv    = (const float*)d_in[8];
    const float* gamma = (const float*)d_in[9];
    float* out = (float*)d_out;

    off_conv_kernel<<<dim3(16, 18, BB), 256>>>(x, w_off, b_off);
    sample_kernel<<<(BB*9*HW)/256, 256>>>(x);
    qk_gemm_kernel<<<dim3(64, BB), 256>>>(wq, bq, wk, bk);
    v_gemm_kernel<<<dim3(4, 32, BB), 256>>>(wv, bv);

    cudaFuncSetAttribute(attn_kernel, cudaFuncAttributeMaxDynamicSharedMemorySize,
                         SMEM_BYTES);
    attn_kernel<<<dim3(64, BB), 256, SMEM_BYTES>>>(x, gamma, out);
}

// round 8
// speedup vs baseline: 2.9698x; 1.1885x over previous
#include <cuda_runtime.h>
#include <cuda_fp16.h>
#include <math.h>
#include <stdint.h>

#define BB 2
#define CC 256
#define HW 4096
#define C8 32
#define CK 2304        // 256*9
#define CHW (CC*HW)
#define VT_ST 72       // padded key-row stride in g_vt / Vs (halves)

// ---------------- scratch (device globals) ----------------
__device__ __align__(16) float g_off[BB*18*HW];
__device__ __align__(16) __half g_Sh[(size_t)BB*CK*HW];   // sampled taps hi (b, ck, p)
__device__ __align__(16) __half g_Sl[(size_t)BB*CK*HW];   // lo
// q/k stored CHANNEL-MAJOR flat [n][p] (raw-reshape semantics), hi/lo fp16
__device__ __align__(16) __half g_qh[BB*C8*HW], g_ql[BB*C8*HW];
__device__ __align__(16) __half g_kh[BB*C8*HW], g_kl[BB*C8*HW];
// v stored pre-transposed per 64-key tile: g_vt[b][kt][ch][klo], fp16
__device__ __align__(16) __half g_vt[(size_t)BB*64*256*VT_ST];

// ---------------- helpers ----------------
__device__ __forceinline__ void mma_f16(float c[4], const uint32_t a[4], const uint32_t b[2]) {
    asm volatile(
        "mma.sync.aligned.m16n8k16.row.col.f32.f16.f16.f32 "
        "{%0,%1,%2,%3}, {%4,%5,%6,%7}, {%8,%9}, {%0,%1,%2,%3};\n"
        : "+f"(c[0]), "+f"(c[1]), "+f"(c[2]), "+f"(c[3])
        : "r"(a[0]), "r"(a[1]), "r"(a[2]), "r"(a[3]), "r"(b[0]), "r"(b[1]));
}
__device__ __forceinline__ void ldsm_x4(uint32_t r[4], const void* p) {
    uint32_t a = (uint32_t)__cvta_generic_to_shared(p);
    asm volatile("ldmatrix.sync.aligned.m8n8.x4.shared.b16 {%0,%1,%2,%3}, [%4];"
        : "=r"(r[0]), "=r"(r[1]), "=r"(r[2]), "=r"(r[3]) : "r"(a));
}
__device__ __forceinline__ void ldsm_x4_trans(uint32_t r[4], const void* p) {
    uint32_t a = (uint32_t)__cvta_generic_to_shared(p);
    asm volatile("ldmatrix.sync.aligned.m8n8.x4.trans.shared.b16 {%0,%1,%2,%3}, [%4];"
        : "=r"(r[0]), "=r"(r[1]), "=r"(r[2]), "=r"(r[3]) : "r"(a));
}
__device__ __forceinline__ void split_f16(float v, __half& h, __half& l) {
    h = __float2half_rn(v);
    l = __float2half_rn(v - __half2float(h));
}

// ---------------- kernel 1: offset conv ----------------
__global__ __launch_bounds__(256)
void off_conv_kernel(const float* __restrict__ x, const float* __restrict__ w,
                     const float* __restrict__ bias) {
    __shared__ float ws[CK];
    int o = blockIdx.y;
    int b = blockIdx.z;
    int p = blockIdx.x * 256 + threadIdx.x;
    for (int i = threadIdx.x; i < CK; i += 256) ws[i] = w[o*CK + i];
    __syncthreads();
    int yy = p >> 6, xx = p & 63;
    const float* xb = x + (size_t)b*CHW;
    float acc = bias[o];
    for (int c = 0; c < CC; c++) {
        const float* xc = xb + c*HW;
        const float* wr = ws + c*9;
        #pragma unroll
        for (int t = 0; t < 9; t++) {
            int y2 = yy + (t/3) - 1;
            int x2 = xx + (t%3) - 1;
            if ((unsigned)y2 < 64u && (unsigned)x2 < 64u)
                acc += xc[y2*64 + x2] * wr[t];
        }
    }
    g_off[((size_t)b*18 + o)*HW + p] = acc;
}

// ---------------- kernel 2: bilinear sampling -> S hi/lo fp16 ----------------
__global__ __launch_bounds__(256)
void sample_kernel(const float* __restrict__ x) {
    int tid = blockIdx.x * 256 + threadIdx.x;
    int p = tid & (HW - 1);
    int t = (tid >> 12) % 9;
    int b = tid / (9*HW);
    int yy = p >> 6, xx = p & 63;
    float dy = g_off[((size_t)b*18 + 2*t    )*HW + p];
    float dx = g_off[((size_t)b*18 + 2*t + 1)*HW + p];
    float py = (float)yy + (float)(t/3 - 1) + dy;
    float px = (float)xx + (float)(t%3 - 1) + dx;
    float y0f = floorf(py), x0f = floorf(px);
    float wy = py - y0f, wx = px - x0f;
    int y0 = (int)y0f, x0 = (int)x0f;
    int y1 = y0 + 1, x1 = x0 + 1;
    bool vy0 = (y0 >= 0) && (y0 < 64), vy1 = (y1 >= 0) && (y1 < 64);
    bool vx0 = (x0 >= 0) && (x0 < 64), vx1 = (x1 >= 0) && (x1 < 64);
    float w00 = (1.f-wy)*(1.f-wx) * (float)(vy0 && vx0);
    float w01 = (1.f-wy)*wx       * (float)(vy0 && vx1);
    float w10 = wy*(1.f-wx)       * (float)(vy1 && vx0);
    float w11 = wy*wx             * (float)(vy1 && vx1);
    int cy0 = min(max(y0,0),63), cy1 = min(max(y1,0),63);
    int cx0 = min(max(x0,0),63), cx1 = min(max(x1,0),63);
    int i00 = cy0*64+cx0, i01 = cy0*64+cx1, i10 = cy1*64+cx0, i11 = cy1*64+cx1;
    const float* xb = x + (size_t)b*CHW;
    size_t base = (size_t)b*CK*HW;
    for (int c = 0; c < CC; c++) {
        const float* xc = xb + c*HW;
        float v = w00*xc[i00] + w01*xc[i01] + w10*xc[i10] + w11*xc[i11];
        __half h, l;
        split_f16(v, h, l);
        size_t idx = base + (size_t)(c*9 + t)*HW + p;
        g_Sh[idx] = h;
        g_Sl[idx] = l;
    }
}

// ---------------- kernel 3: q,k GEMM, D[n][p] channel-major, 3-pass split fp16 ----------------
#define SM_ST 34
__global__ __launch_bounds__(256)
void qk_gemm_kernel(const float* __restrict__ Wq, const float* __restrict__ bq,
                    const float* __restrict__ Wk, const float* __restrict__ bk) {
    __shared__ __half Sh[64][SM_ST], Sl[64][SM_ST];
    __shared__ __half Whs[64][SM_ST], Wls[64][SM_ST];
    int b  = blockIdx.y;
    int p0 = blockIdx.x * 64;
    int t = threadIdx.x, lane = t & 31, w = t >> 5;
    int g = lane >> 2, tq = lane & 3;
    int wn = w >> 1, wp = w & 1;       // warp: 16 n-rows x 32 p-cols
    int n0 = 16*wn, pc0 = 32*wp;
    size_t sbase = (size_t)b*CK*HW;

    float acc[4][4];
    #pragma unroll
    for (int i = 0; i < 4; i++)
        #pragma unroll
        for (int j = 0; j < 4; j++) acc[i][j] = 0.f;

    for (int k0 = 0; k0 < CK; k0 += 32) {
        for (int i = t; i < 1024; i += 256) {       // S^T: 32k x 64p -> [p][k]
            int kk = i >> 5, pl = (i & 31) * 2;
            size_t gi = sbase + (size_t)(k0 + kk)*HW + p0 + pl;
            __half2 vh = *(const __half2*)(g_Sh + gi);
            __half2 vl = *(const __half2*)(g_Sl + gi);
            Sh[pl][kk] = vh.x; Sh[pl+1][kk] = vh.y;
            Sl[pl][kk] = vl.x; Sl[pl+1][kk] = vl.y;
        }
        for (int i = t; i < 2048; i += 256) {       // W: 64n x 32k, hi/lo
            int m = i >> 5, kk = i & 31;
            const float* Wsrc = (m < 32) ? (Wq + (size_t)m*CK) : (Wk + (size_t)(m-32)*CK);
            float v = Wsrc[k0 + kk];
            split_f16(v, Whs[m][kk], Wls[m][kk]);
        }
        __syncthreads();

        uint32_t Ah[2][4], Al[2][4];
        int ar = n0 + g;
        #pragma unroll
        for (int ks = 0; ks < 2; ks++) {
            int kc = ks*16 + 2*tq;
            Ah[ks][0] = *(const uint32_t*)&Whs[ar    ][kc  ];
            Ah[ks][1] = *(const uint32_t*)&Whs[ar + 8][kc  ];
            Ah[ks][2] = *(const uint32_t*)&Whs[ar    ][kc+8];
            Ah[ks][3] = *(const uint32_t*)&Whs[ar + 8][kc+8];
            Al[ks][0] = *(const uint32_t*)&Wls[ar    ][kc  ];
            Al[ks][1] = *(const uint32_t*)&Wls[ar + 8][kc  ];
            Al[ks][2] = *(const uint32_t*)&Wls[ar    ][kc+8];
            Al[ks][3] = *(const uint32_t*)&Wls[ar + 8][kc+8];
        }
        #pragma unroll
        for (int nf = 0; nf < 4; nf++) {
            int pcol = pc0 + 8*nf + g;
            #pragma unroll
            for (int ks = 0; ks < 2; ks++) {
                int kc = ks*16 + 2*tq;
                uint32_t Bh[2], Bl[2];
                Bh[0] = *(const uint32_t*)&Sh[pcol][kc  ];
                Bh[1] = *(const uint32_t*)&Sh[pcol][kc+8];
                Bl[0] = *(const uint32_t*)&Sl[pcol][kc  ];
                Bl[1] = *(const uint32_t*)&Sl[pcol][kc+8];
                mma_f16(acc[nf], Ah[ks], Bh);
                mma_f16(acc[nf], Ah[ks], Bl);
                mma_f16(acc[nf], Al[ks], Bh);
            }
        }
        __syncthreads();
    }
    #pragma unroll
    for (int half = 0; half < 2; half++) {
        int n = n0 + g + 8*half;
        float bz = (n < 32) ? bq[n] : bk[n - 32];
        __half* dh = (n < 32) ? (g_qh + ((size_t)b*C8 + n)*HW)
                              : (g_kh + ((size_t)b*C8 + n - 32)*HW);
        __half* dl = (n < 32) ? (g_ql + ((size_t)b*C8 + n)*HW)
                              : (g_kl + ((size_t)b*C8 + n - 32)*HW);
        #pragma unroll
        for (int nf = 0; nf < 4; nf++) {
            int p = p0 + pc0 + 8*nf + 2*tq;
            float v0 = acc[nf][2*half]   + bz;
            float v1 = acc[nf][2*half+1] + bz;
            __half h0,l0,h1,l1;
            split_f16(v0, h0, l0); split_f16(v1, h1, l1);
            *(__half2*)(dh + p) = __half2{h0, h1};
            *(__half2*)(dl + p) = __half2{l0, l1};
        }
    }
}

// ---------------- kernel 4: v GEMM single-pass fp16 + ldmatrix ----------------
#define VW_ST 40    // W smem stride (halves): 32 + 8 pad
#define VS_ST 136   // S smem stride (halves): 128 + 8 pad
__global__ __launch_bounds__(256)
void v_gemm_kernel(const float* __restrict__ Wv, const float* __restrict__ bv) {
    __shared__ __half Wsm[64][VW_ST];
    __shared__ __half Ssm[32][VS_ST];
    int b  = blockIdx.z;
    int m0 = blockIdx.x * 64;
    int p0 = blockIdx.y * 128;
    int t = threadIdx.x, lane = t & 31, w = t >> 5;
    int g = lane >> 2, tq = lane & 3;
    int wm = w >> 2, wn = w & 3;       // warp: 32 m-rows x 32 p-cols
    size_t sbase = (size_t)b*CK*HW;

    float acc[2][4][4];
    #pragma unroll
    for (int a = 0; a < 2; a++)
        #pragma unroll
        for (int i = 0; i < 4; i++)
            #pragma unroll
            for (int j = 0; j < 4; j++) acc[a][i][j] = 0.f;

    int l7  = lane & 7;
    int lb3 = (lane >> 3) & 1;
    int lb4 = (lane >> 4) & 1;

    for (int k0 = 0; k0 < CK; k0 += 32) {
        // stage S [32k][128p]: contiguous uint4 copy, no transpose
        for (int i = t; i < 512; i += 256) {
            int kk = i >> 4, seg = i & 15;
            uint4 v = *(const uint4*)(g_Sh + sbase + (size_t)(k0 + kk)*HW + p0 + seg*8);
            *(uint4*)(&Ssm[kk][seg*8]) = v;
        }
        // stage W [64m][32k] fp32 -> fp16
        for (int i = t; i < 512; i += 256) {
            int m = i >> 3, seg = i & 7;
            float4 v = *(const float4*)(Wv + (size_t)(m0 + m)*CK + k0 + seg*4);
            __half2 h0 = __floats2half2_rn(v.x, v.y);
            __half2 h1 = __floats2half2_rn(v.z, v.w);
            *(__half2*)&Wsm[m][seg*4]     = h0;
            *(__half2*)&Wsm[m][seg*4 + 2] = h1;
        }
        __syncthreads();

        #pragma unroll
        for (int ks = 0; ks < 2; ks++) {
            uint32_t A[2][4];
            #pragma unroll
            for (int mf = 0; mf < 2; mf++) {
                int row = 32*wm + 16*mf + l7 + lb3*8;
                int col = 16*ks + lb4*8;
                ldsm_x4(A[mf], &Wsm[row][col]);
            }
            #pragma unroll
            for (int nfp = 0; nfp < 2; nfp++) {
                int row = 16*ks + l7 + lb3*8;
                int col = 32*wn + 16*nfp + lb4*8;
                uint32_t Bf[4];
                ldsm_x4_trans(Bf, &Ssm[row][col]);
                mma_f16(acc[0][2*nfp    ], A[0], &Bf[0]);
                mma_f16(acc[0][2*nfp + 1], A[0], &Bf[2]);
                mma_f16(acc[1][2*nfp    ], A[1], &Bf[0]);
                mma_f16(acc[1][2*nfp + 1], A[1], &Bf[2]);
            }
        }
        __syncthreads();
    }
    // epilogue: raw-flat j = m*4096+p -> V'[key][ch]; key = m*16 + (p0>>8), ch = p&255
    int phi = p0 >> 8;
    #pragma unroll
    for (int mf = 0; mf < 2; mf++) {
        #pragma unroll
        for (int half = 0; half < 2; half++) {
            int m = m0 + 32*wm + 16*mf + g + 8*half;
            float bz = bv[m];
            int key = m*16 + phi;
            size_t tbase = ((size_t)b*64 + (key >> 6))*(256*VT_ST) + (key & 63);
            #pragma unroll
            for (int nf = 0; nf < 4; nf++) {
                int p = p0 + 32*wn + 8*nf + 2*tq;
                int ch0 = p & 255;
                float v0 = acc[mf][nf][2*half]   + bz;
                float v1 = acc[mf][nf][2*half+1] + bz;
                g_vt[tbase + (size_t)ch0*VT_ST]     = __float2half_rn(v0);
                g_vt[tbase + (size_t)(ch0+1)*VT_ST] = __float2half_rn(v1);
            }
        }
    }
}

// ---------------- kernel 5: flash attention + fused epilogue ----------------
#define SMEM_BYTES (64*VT_ST*4 + 64*VT_ST*2 + 256*VT_ST*2 + 3*64*4)

__global__ __launch_bounds__(256)
void attn_kernel(const float* __restrict__ x, const float* __restrict__ gamma,
                 float* __restrict__ out) {
    extern __shared__ char smem_raw[];
    float* Ps = (float*)smem_raw;
    __half* Pb = (__half*)(Ps + 64*VT_ST);
    __half* Vs = Pb + 64*VT_ST;
    float* rowm = (float*)(Vs + 256*VT_ST);
    float* rowl = rowm + 64;
    float* rowa = rowl + 64;

    int b  = blockIdx.y;
    int q0 = blockIdx.x * 64;
    int t = threadIdx.x, lane = t & 31, w = t >> 5;
    int g = lane >> 2, tq = lane & 3;
    int wq = w >> 1, wh = w & 1;
    int l7  = lane & 7;
    int lb3 = (lane >> 3) & 1;
    int lb4 = (lane >> 4) & 1;

    const __half* Qh = g_qh + (size_t)b*C8*HW;   // flat raw-reshape row-major (4096,32)
    const __half* Ql = g_ql + (size_t)b*C8*HW;
    const __half* Kh = g_kh + (size_t)b*C8*HW;
    const __half* Kl = g_kl + (size_t)b*C8*HW;
    const __half* Vt = g_vt + (size_t)b*64*256*VT_ST;

    uint32_t qAh[2][4], qAl[2][4];
    {
        int qrow = q0 + 16*wq + g;
        #pragma unroll
        for (int ks = 0; ks < 2; ks++) {
            int kc = ks*16 + 2*tq;
            qAh[ks][0] = *(const uint32_t*)(Qh + (size_t)qrow*32 + kc);
            qAh[ks][1] = *(const uint32_t*)(Qh + (size_t)(qrow+8)*32 + kc);
            qAh[ks][2] = *(const uint32_t*)(Qh + (size_t)qrow*32 + kc + 8);
            qAh[ks][3] = *(const uint32_t*)(Qh + (size_t)(qrow+8)*32 + kc + 8);
            qAl[ks][0] = *(const uint32_t*)(Ql + (size_t)qrow*32 + kc);
            qAl[ks][1] = *(const uint32_t*)(Ql + (size_t)(qrow+8)*32 + kc);
            qAl[ks][2] = *(const uint32_t*)(Ql + (size_t)qrow*32 + kc + 8);
            qAl[ks][3] = *(const uint32_t*)(Ql + (size_t)(qrow+8)*32 + kc + 8);
        }
    }
    if (t < 64) { rowm[t] = -1e30f; rowl[t] = 0.f; }

    float O[16][4];
    #pragma unroll
    for (int i = 0; i < 16; i++)
        #pragma unroll
        for (int j = 0; j < 4; j++) O[i][j] = 0.f;
    __syncthreads();

    for (int kt = 0; kt < 64; kt++) {
        // stage V' tile [ch][key] — contiguous copy
        {
            const __half* src = Vt + (size_t)kt*256*VT_ST;
            for (int i = t; i < 2048; i += 256) {
                int c = i >> 3, seg = i & 7;
                uint4 vv = *(const uint4*)(src + c*VT_ST + seg*8);
                *(uint4*)(Vs + c*VT_ST + seg*8) = vv;
            }
        }
        // QK logits (3-pass split fp16)
        float qacc[4][4];
        #pragma unroll
        for (int i = 0; i < 4; i++)
            #pragma unroll
            for (int j = 0; j < 4; j++) qacc[i][j] = 0.f;
        #pragma unroll
        for (int nf = 0; nf < 4; nf++) {
            int key = kt*64 + 32*wh + 8*nf + g;
            #pragma unroll
            for (int ks = 0; ks < 2; ks++) {
                int kc = ks*16 + 2*tq;
                uint32_t Bh[2], Bl[2];
                Bh[0] = *(const uint32_t*)(Kh + (size_t)key*32 + kc);
                Bh[1] = *(const uint32_t*)(Kh + (size_t)key*32 + kc + 8);
                Bl[0] = *(const uint32_t*)(Kl + (size_t)key*32 + kc);
                Bl[1] = *(const uint32_t*)(Kl + (size_t)key*32 + kc + 8);
                mma_f16(qacc[nf], qAh[ks], Bh);
                mma_f16(qacc[nf], qAh[ks], Bl);
                mma_f16(qacc[nf], qAl[ks], Bh);
            }
        }
        {
            int pr = 16*wq + g;
            #pragma unroll
            for (int nf = 0; nf < 4; nf++) {
                int pc = 32*wh + 8*nf + 2*tq;
                Ps[pr*VT_ST + pc]       = qacc[nf][0];
                Ps[pr*VT_ST + pc + 1]   = qacc[nf][1];
                Ps[(pr+8)*VT_ST + pc]   = qacc[nf][2];
                Ps[(pr+8)*VT_ST + pc+1] = qacc[nf][3];
            }
        }
        __syncthreads();
        // online softmax: 4 threads/row
        {
            int r = t >> 2, sg = t & 3;
            const float* pr = Ps + r*VT_ST + sg*16;
            float mx = -1e30f;
            #pragma unroll
            for (int j = 0; j < 16; j++) mx = fmaxf(mx, pr[j]);
            mx = fmaxf(mx, __shfl_xor_sync(0xffffffffu, mx, 1));
            mx = fmaxf(mx, __shfl_xor_sync(0xffffffffu, mx, 2));
            float mold = rowm[r];
            float mnew = fmaxf(mold, mx);
            float s = 0.f;
            __half* pb = Pb + r*VT_ST + sg*16;
            #pragma unroll
            for (int j = 0; j < 16; j++) {
                float e = __expf(pr[j] - mnew);
                s += e;
                pb[j] = __float2half_rn(e);
            }
            s += __shfl_xor_sync(0xffffffffu, s, 1);
            s += __shfl_xor_sync(0xffffffffu, s, 2);
            if (sg == 0) {
                float alpha = __expf(mold - mnew);
                rowm[r] = mnew;
                rowl[r] = rowl[r]*alpha + s;
                rowa[r] = alpha;
            }
        }
        __syncthreads();
        // PV: O = O*alpha + P @ V'  (fp16, ldmatrix frags)
        {
            float al0 = rowa[16*wq + g];
            float al1 = rowa[16*wq + g + 8];
            #pragma unroll
            for (int nf = 0; nf < 16; nf++) {
                O[nf][0] *= al0; O[nf][1] *= al0;
                O[nf][2] *= al1; O[nf][3] *= al1;
            }
            #pragma unroll
            for (int ks = 0; ks < 4; ks++) {
                uint32_t pA[4];
                {
                    int row = 16*wq + l7 + lb3*8;
                    int col = 16*ks + lb4*8;
                    ldsm_x4(pA, Pb + row*VT_ST + col);
                }
                #pragma unroll
                for (int nfp = 0; nfp < 8; nfp++) {
                    int row = 128*wh + 16*nfp + l7 + lb4*8;   // ch
                    int col = 16*ks + lb3*8;                  // key
                    uint32_t Bf[4];
                    ldsm_x4(Bf, Vs + row*VT_ST + col);
                    mma_f16(O[2*nfp    ], pA, &Bf[0]);
                    mma_f16(O[2*nfp + 1], pA, &Bf[2]);
                }
            }
        }
        __syncthreads();
    }
    // epilogue: gamma * O/l + x  (raw-reshape flat indexing)
    {
        float gm = gamma[0];
        int row0 = q0 + 16*wq + g;
        float inv0 = 1.f / rowl[16*wq + g];
        float inv1 = 1.f / rowl[16*wq + g + 8];
        #pragma unroll
        for (int nf = 0; nf < 16; nf++) {
            int ch = 128*wh + 8*nf + 2*tq;
            size_t i0 = (size_t)b*CHW + (size_t)row0*256 + ch;
            size_t i1 = (size_t)b*CHW + (size_t)(row0+8)*256 + ch;
            out[i0]   = gm*O[nf][0]*inv0 + x[i0];
            out[i0+1] = gm*O[nf][1]*inv0 + x[i0+1];
            out[i1]   = gm*O[nf][2]*inv1 + x[i1];
            out[i1+1] = gm*O[nf][3]*inv1 + x[i1+1];
        }
    }
}

// ---------------- launch ----------------
extern "C" void kernel_launch(void* const* d_in, const int* in_sizes, int n_in,
                              void* d_out, int out_size) {
    const float* x     = (const float*)d_in[0];
    const float* w_off = (const float*)d_in[1];
    const float* b_off = (const float*)d_in[2];
    const float* wq    = (const float*)d_in[3];
    const float* bq    = (const float*)d_in[4];
    const float* wk    = (const float*)d_in[5];
    const float* bk    = (const float*)d_in[6];
    const float* wv    = (const float*)d_in[7];
    const float* bv    = (const float*)d_in[8];
    const float* gamma = (const float*)d_in[9];
    float* out = (float*)d_out;

    off_conv_kernel<<<dim3(16, 18, BB), 256>>>(x, w_off, b_off);
    sample_kernel<<<(BB*9*HW)/256, 256>>>(x);
    qk_gemm_kernel<<<dim3(64, BB), 256>>>(wq, bq, wk, bk);
    v_gemm_kernel<<<dim3(4, 32, BB), 256>>>(wv, bv);

    cudaFuncSetAttribute(attn_kernel, cudaFuncAttributeMaxDynamicSharedMemorySize,
                         SMEM_BYTES);
    attn_kernel<<<dim3(64, BB), 256, SMEM_BYTES>>>(x, gamma, out);
}

// round 10
// speedup vs baseline: 3.6820x; 1.2398x over previous
#include <cuda_runtime.h>
#include <cuda_fp16.h>
#include <math.h>
#include <stdint.h>

#define BB 2
#define CC 256
#define HW 4096
#define C8 32
#define CK 2304        // 256*9
#define CHW (CC*HW)
#define VT_ST 72       // padded key-row stride in g_vt / Vs (halves)

// ---------------- scratch (device globals) ----------------
__device__ __align__(16) float g_off[BB*18*HW];
__device__ __align__(16) __half g_Sh[(size_t)BB*CK*HW];   // sampled taps hi (b, ck, p)
__device__ __align__(16) __half g_Sl[(size_t)BB*CK*HW];   // lo
// q/k stored CHANNEL-MAJOR flat [n][p] (raw-reshape semantics), hi/lo fp16
__device__ __align__(16) __half g_qh[BB*C8*HW], g_ql[BB*C8*HW];
__device__ __align__(16) __half g_kh[BB*C8*HW], g_kl[BB*C8*HW];
// v stored pre-transposed per 64-key tile: g_vt[b][kt][ch][klo], fp16
__device__ __align__(16) __half g_vt[(size_t)BB*64*256*VT_ST];
// pre-converted fp16 V-weights
__device__ __align__(16) __half g_Wvh[CC*CK];

// ---------------- helpers ----------------
__device__ __forceinline__ void mma_f16(float c[4], const uint32_t a[4], const uint32_t b[2]) {
    asm volatile(
        "mma.sync.aligned.m16n8k16.row.col.f32.f16.f16.f32 "
        "{%0,%1,%2,%3}, {%4,%5,%6,%7}, {%8,%9}, {%0,%1,%2,%3};\n"
        : "+f"(c[0]), "+f"(c[1]), "+f"(c[2]), "+f"(c[3])
        : "r"(a[0]), "r"(a[1]), "r"(a[2]), "r"(a[3]), "r"(b[0]), "r"(b[1]));
}
__device__ __forceinline__ void ldsm_x4(uint32_t r[4], const void* p) {
    uint32_t a = (uint32_t)__cvta_generic_to_shared(p);
    asm volatile("ldmatrix.sync.aligned.m8n8.x4.shared.b16 {%0,%1,%2,%3}, [%4];"
        : "=r"(r[0]), "=r"(r[1]), "=r"(r[2]), "=r"(r[3]) : "r"(a));
}
__device__ __forceinline__ void ldsm_x4_trans(uint32_t r[4], const void* p) {
    uint32_t a = (uint32_t)__cvta_generic_to_shared(p);
    asm volatile("ldmatrix.sync.aligned.m8n8.x4.trans.shared.b16 {%0,%1,%2,%3}, [%4];"
        : "=r"(r[0]), "=r"(r[1]), "=r"(r[2]), "=r"(r[3]) : "r"(a));
}
__device__ __forceinline__ void split_f16(float v, __half& h, __half& l) {
    h = __float2half_rn(v);
    l = __float2half_rn(v - __half2float(h));
}
__device__ __forceinline__ void cpa16(void* smem, const void* gmem) {
    uint32_t s = (uint32_t)__cvta_generic_to_shared(smem);
    asm volatile("cp.async.cg.shared.global [%0], [%1], 16;\n" :: "r"(s), "l"(gmem));
}
__device__ __forceinline__ void cpa_commit() {
    asm volatile("cp.async.commit_group;\n");
}
template<int N> __device__ __forceinline__ void cpa_wait() {
    asm volatile("cp.async.wait_group %0;\n" :: "n"(N));
}

// ---------------- kernel 0: pre-convert Wv -> fp16 ----------------
__global__ __launch_bounds__(256)
void prep_wv_kernel(const float* __restrict__ Wv) {
    int i = (blockIdx.x * 256 + threadIdx.x) * 4;
    float4 v = *(const float4*)(Wv + i);
    __half2 h0 = __floats2half2_rn(v.x, v.y);
    __half2 h1 = __floats2half2_rn(v.z, v.w);
    *(__half2*)(g_Wvh + i)     = h0;
    *(__half2*)(g_Wvh + i + 2) = h1;
}

// ---------------- kernel 1: offset conv ----------------
__global__ __launch_bounds__(256)
void off_conv_kernel(const float* __restrict__ x, const float* __restrict__ w,
                     const float* __restrict__ bias) {
    __shared__ float ws[CK];
    int o = blockIdx.y;
    int b = blockIdx.z;
    int p = blockIdx.x * 256 + threadIdx.x;
    for (int i = threadIdx.x; i < CK; i += 256) ws[i] = w[o*CK + i];
    __syncthreads();
    int yy = p >> 6, xx = p & 63;
    const float* xb = x + (size_t)b*CHW;
    float acc = bias[o];
    for (int c = 0; c < CC; c++) {
        const float* xc = xb + c*HW;
        const float* wr = ws + c*9;
        #pragma unroll
        for (int t = 0; t < 9; t++) {
            int y2 = yy + (t/3) - 1;
            int x2 = xx + (t%3) - 1;
            if ((unsigned)y2 < 64u && (unsigned)x2 < 64u)
                acc += xc[y2*64 + x2] * wr[t];
        }
    }
    g_off[((size_t)b*18 + o)*HW + p] = acc;
}

// ---------------- kernel 2: bilinear sampling -> S hi/lo fp16 (c-sliced) ----------------
__global__ __launch_bounds__(256)
void sample_kernel(const float* __restrict__ x) {
    int tid = blockIdx.x * 256 + threadIdx.x;
    int cslice = blockIdx.y;               // 0..3, 64 channels each
    int p = tid & (HW - 1);
    int t = (tid >> 12) % 9;
    int b = tid / (9*HW);
    int yy = p >> 6, xx = p & 63;
    float dy = g_off[((size_t)b*18 + 2*t    )*HW + p];
    float dx = g_off[((size_t)b*18 + 2*t + 1)*HW + p];
    float py = (float)yy + (float)(t/3 - 1) + dy;
    float px = (float)xx + (float)(t%3 - 1) + dx;
    float y0f = floorf(py), x0f = floorf(px);
    float wy = py - y0f, wx = px - x0f;
    int y0 = (int)y0f, x0 = (int)x0f;
    int y1 = y0 + 1, x1 = x0 + 1;
    bool vy0 = (y0 >= 0) && (y0 < 64), vy1 = (y1 >= 0) && (y1 < 64);
    bool vx0 = (x0 >= 0) && (x0 < 64), vx1 = (x1 >= 0) && (x1 < 64);
    float w00 = (1.f-wy)*(1.f-wx) * (float)(vy0 && vx0);
    float w01 = (1.f-wy)*wx       * (float)(vy0 && vx1);
    float w10 = wy*(1.f-wx)       * (float)(vy1 && vx0);
    float w11 = wy*wx             * (float)(vy1 && vx1);
    int cy0 = min(max(y0,0),63), cy1 = min(max(y1,0),63);
    int cx0 = min(max(x0,0),63), cx1 = min(max(x1,0),63);
    int i00 = cy0*64+cx0, i01 = cy0*64+cx1, i10 = cy1*64+cx0, i11 = cy1*64+cx1;
    const float* xb = x + (size_t)b*CHW;
    size_t base = (size_t)b*CK*HW;
    int c0 = cslice * 64;
    #pragma unroll 4
    for (int c = c0; c < c0 + 64; c++) {
        const float* xc = xb + c*HW;
        float v = w00*xc[i00] + w01*xc[i01] + w10*xc[i10] + w11*xc[i11];
        __half h, l;
        split_f16(v, h, l);
        size_t idx = base + (size_t)(c*9 + t)*HW + p;
        g_Sh[idx] = h;
        g_Sl[idx] = l;
    }
}

// ---------------- kernel 3: q,k GEMM, D[n][p] channel-major, 3-pass split fp16 ----------------
#define SM_ST 34
__global__ __launch_bounds__(256)
void qk_gemm_kernel(const float* __restrict__ Wq, const float* __restrict__ bq,
                    const float* __restrict__ Wk, const float* __restrict__ bk) {
    __shared__ __half Sh[64][SM_ST], Sl[64][SM_ST];
    __shared__ __half Whs[64][SM_ST], Wls[64][SM_ST];
    int b  = blockIdx.y;
    int p0 = blockIdx.x * 64;
    int t = threadIdx.x, lane = t & 31, w = t >> 5;
    int g = lane >> 2, tq = lane & 3;
    int wn = w >> 1, wp = w & 1;       // warp: 16 n-rows x 32 p-cols
    int n0 = 16*wn, pc0 = 32*wp;
    size_t sbase = (size_t)b*CK*HW;

    float acc[4][4];
    #pragma unroll
    for (int i = 0; i < 4; i++)
        #pragma unroll
        for (int j = 0; j < 4; j++) acc[i][j] = 0.f;

    for (int k0 = 0; k0 < CK; k0 += 32) {
        for (int i = t; i < 1024; i += 256) {       // S^T: 32k x 64p -> [p][k]
            int kk = i >> 5, pl = (i & 31) * 2;
            size_t gi = sbase + (size_t)(k0 + kk)*HW + p0 + pl;
            __half2 vh = *(const __half2*)(g_Sh + gi);
            __half2 vl = *(const __half2*)(g_Sl + gi);
            Sh[pl][kk] = vh.x; Sh[pl+1][kk] = vh.y;
            Sl[pl][kk] = vl.x; Sl[pl+1][kk] = vl.y;
        }
        for (int i = t; i < 2048; i += 256) {       // W: 64n x 32k, hi/lo
            int m = i >> 5, kk = i & 31;
            const float* Wsrc = (m < 32) ? (Wq + (size_t)m*CK) : (Wk + (size_t)(m-32)*CK);
            float v = Wsrc[k0 + kk];
            split_f16(v, Whs[m][kk], Wls[m][kk]);
        }
        __syncthreads();

        uint32_t Ah[2][4], Al[2][4];
        int ar = n0 + g;
        #pragma unroll
        for (int ks = 0; ks < 2; ks++) {
            int kc = ks*16 + 2*tq;
            Ah[ks][0] = *(const uint32_t*)&Whs[ar    ][kc  ];
            Ah[ks][1] = *(const uint32_t*)&Whs[ar + 8][kc  ];
            Ah[ks][2] = *(const uint32_t*)&Whs[ar    ][kc+8];
            Ah[ks][3] = *(const uint32_t*)&Whs[ar + 8][kc+8];
            Al[ks][0] = *(const uint32_t*)&Wls[ar    ][kc  ];
            Al[ks][1] = *(const uint32_t*)&Wls[ar + 8][kc  ];
            Al[ks][2] = *(const uint32_t*)&Wls[ar    ][kc+8];
            Al[ks][3] = *(const uint32_t*)&Wls[ar + 8][kc+8];
        }
        #pragma unroll
        for (int nf = 0; nf < 4; nf++) {
            int pcol = pc0 + 8*nf + g;
            #pragma unroll
            for (int ks = 0; ks < 2; ks++) {
                int kc = ks*16 + 2*tq;
                uint32_t Bh[2], Bl[2];
                Bh[0] = *(const uint32_t*)&Sh[pcol][kc  ];
                Bh[1] = *(const uint32_t*)&Sh[pcol][kc+8];
                Bl[0] = *(const uint32_t*)&Sl[pcol][kc  ];
                Bl[1] = *(const uint32_t*)&Sl[pcol][kc+8];
                mma_f16(acc[nf], Ah[ks], Bh);
                mma_f16(acc[nf], Ah[ks], Bl);
                mma_f16(acc[nf], Al[ks], Bh);
            }
        }
        __syncthreads();
    }
    #pragma unroll
    for (int half = 0; half < 2; half++) {
        int n = n0 + g + 8*half;
        float bz = (n < 32) ? bq[n] : bk[n - 32];
        __half* dh = (n < 32) ? (g_qh + ((size_t)b*C8 + n)*HW)
                              : (g_kh + ((size_t)b*C8 + n - 32)*HW);
        __half* dl = (n < 32) ? (g_ql + ((size_t)b*C8 + n)*HW)
                              : (g_kl + ((size_t)b*C8 + n - 32)*HW);
        #pragma unroll
        for (int nf = 0; nf < 4; nf++) {
            int p = p0 + pc0 + 8*nf + 2*tq;
            float v0 = acc[nf][2*half]   + bz;
            float v1 = acc[nf][2*half+1] + bz;
            __half h0,l0,h1,l1;
            split_f16(v0, h0, l0); split_f16(v1, h1, l1);
            *(__half2*)(dh + p) = __half2{h0, h1};
            *(__half2*)(dl + p) = __half2{l0, l1};
        }
    }
}

// ---------------- kernel 4: v GEMM fp16, 4-stage cp.async pipeline ----------------
#define VW_ST 40    // W smem stride (halves): 32 + 8 pad (80B, 16B-mult)
#define VS_ST 136   // S smem stride (halves): 128 + 8 pad (272B, 16B-mult)
#define NKT 72      // CK/32
__global__ __launch_bounds__(256)
void v_gemm_kernel(const float* __restrict__ Wv_unused, const float* __restrict__ bv) {
    __shared__ __half Wsm[4][64][VW_ST];
    __shared__ __half Ssm[4][32][VS_ST];
    int b  = blockIdx.z;
    int m0 = blockIdx.x * 64;
    int p0 = blockIdx.y * 128;
    int t = threadIdx.x, lane = t & 31, w = t >> 5;
    int g = lane >> 2, tq = lane & 3;
    int wm = w >> 2, wn = w & 3;       // warp: 32 m-rows x 32 p-cols
    size_t sbase = (size_t)b*CK*HW;

    float acc[2][4][4];
    #pragma unroll
    for (int a = 0; a < 2; a++)
        #pragma unroll
        for (int i = 0; i < 4; i++)
            #pragma unroll
            for (int j = 0; j < 4; j++) acc[a][i][j] = 0.f;

    int l7  = lane & 7;
    int lb3 = (lane >> 3) & 1;
    int lb4 = (lane >> 4) & 1;

    // stage issuer: tile kt -> buffer st
    auto issue = [&](int kt, int st) {
        int k0 = kt * 32;
        // S: 32 rows x 128 halves = 512 x 16B; 2 chunks/thread
        #pragma unroll
        for (int r = 0; r < 2; r++) {
            int i = t + r*256;
            int kk = i >> 4, seg = i & 15;
            cpa16(&Ssm[st][kk][seg*8],
                  g_Sh + sbase + (size_t)(k0 + kk)*HW + p0 + seg*8);
        }
        // W: 64 rows x 32 halves = 256 x 16B; 1 chunk/thread
        {
            int m = t >> 2, seg = t & 3;
            cpa16(&Wsm[st][m][seg*8],
                  g_Wvh + (size_t)(m0 + m)*CK + k0 + seg*8);
        }
    };

    issue(0, 0); cpa_commit();
    issue(1, 1); cpa_commit();
    issue(2, 2); cpa_commit();

    for (int it = 0; it < NKT; it++) {
        if (it + 3 < NKT) issue(it + 3, (it + 3) & 3);
        cpa_commit();                 // always commit (empty at tail keeps count)
        cpa_wait<3>();
        __syncthreads();
        int st = it & 3;

        #pragma unroll
        for (int ks = 0; ks < 2; ks++) {
            uint32_t A[2][4];
            #pragma unroll
            for (int mf = 0; mf < 2; mf++) {
                int row = 32*wm + 16*mf + l7 + lb3*8;
                int col = 16*ks + lb4*8;
                ldsm_x4(A[mf], &Wsm[st][row][col]);
            }
            #pragma unroll
            for (int nfp = 0; nfp < 2; nfp++) {
                int row = 16*ks + l7 + lb3*8;
                int col = 32*wn + 16*nfp + lb4*8;
                uint32_t Bf[4];
                ldsm_x4_trans(Bf, &Ssm[st][row][col]);
                mma_f16(acc[0][2*nfp    ], A[0], &Bf[0]);
                mma_f16(acc[0][2*nfp + 1], A[0], &Bf[2]);
                mma_f16(acc[1][2*nfp    ], A[1], &Bf[0]);
                mma_f16(acc[1][2*nfp + 1], A[1], &Bf[2]);
            }
        }
        __syncthreads();
    }
    // epilogue: raw-flat j = m*4096+p -> V'[key][ch]; key = m*16 + (p0>>8), ch = p&255
    int phi = p0 >> 8;
    #pragma unroll
    for (int mf = 0; mf < 2; mf++) {
        #pragma unroll
        for (int half = 0; half < 2; half++) {
            int m = m0 + 32*wm + 16*mf + g + 8*half;
            float bz = bv[m];
            int key = m*16 + phi;
            size_t tbase = ((size_t)b*64 + (key >> 6))*(256*VT_ST) + (key & 63);
            #pragma unroll
            for (int nf = 0; nf < 4; nf++) {
                int p = p0 + 32*wn + 8*nf + 2*tq;
                int ch0 = p & 255;
                float v0 = acc[mf][nf][2*half]   + bz;
                float v1 = acc[mf][nf][2*half+1] + bz;
                g_vt[tbase + (size_t)ch0*VT_ST]     = __float2half_rn(v0);
                g_vt[tbase + (size_t)(ch0+1)*VT_ST] = __float2half_rn(v1);
            }
        }
    }
}

// ---------------- kernel 5: flash attention, 2-stage cp.async pipeline ----------------
#define KK_ST 40    // K smem stride (halves): 32 + 8 pad
// dynamic smem layout (halves-based offsets computed at runtime):
// Ps fp32[64*72] | Pb f16[64*72] | Vs f16[2][256*72] | Kh f16[2][64*40] | Kl f16[2][64*40] | rows
#define SMEM_BYTES (64*VT_ST*4 + 64*VT_ST*2 + 2*256*VT_ST*2 + 2*64*KK_ST*2*2 + 3*64*4)

__global__ __launch_bounds__(256)
void attn_kernel(const float* __restrict__ x, const float* __restrict__ gamma,
                 float* __restrict__ out) {
    extern __shared__ char smem_raw[];
    float* Ps = (float*)smem_raw;
    __half* Pb  = (__half*)(Ps + 64*VT_ST);
    __half* Vs0 = Pb + 64*VT_ST;
    __half* Kh0 = Vs0 + 2*256*VT_ST;
    __half* Kl0 = Kh0 + 2*64*KK_ST;
    float* rowm = (float*)(Kl0 + 2*64*KK_ST);
    float* rowl = rowm + 64;
    float* rowa = rowl + 64;

    int b  = blockIdx.y;
    int q0 = blockIdx.x * 64;
    int t = threadIdx.x, lane = t & 31, w = t >> 5;
    int g = lane >> 2, tq = lane & 3;
    int wq = w >> 1, wh = w & 1;
    int l7  = lane & 7;
    int lb3 = (lane >> 3) & 1;
    int lb4 = (lane >> 4) & 1;

    const __half* Qh = g_qh + (size_t)b*C8*HW;   // flat raw-reshape row-major (4096,32)
    const __half* Ql = g_ql + (size_t)b*C8*HW;
    const __half* Khg = g_kh + (size_t)b*C8*HW;
    const __half* Klg = g_kl + (size_t)b*C8*HW;
    const __half* Vt = g_vt + (size_t)b*64*256*VT_ST;

    uint32_t qAh[2][4], qAl[2][4];
    {
        int qrow = q0 + 16*wq + g;
        #pragma unroll
        for (int ks = 0; ks < 2; ks++) {
            int kc = ks*16 + 2*tq;
            qAh[ks][0] = *(const uint32_t*)(Qh + (size_t)qrow*32 + kc);
            qAh[ks][1] = *(const uint32_t*)(Qh + (size_t)(qrow+8)*32 + kc);
            qAh[ks][2] = *(const uint32_t*)(Qh + (size_t)qrow*32 + kc + 8);
            qAh[ks][3] = *(const uint32_t*)(Qh + (size_t)(qrow+8)*32 + kc + 8);
            qAl[ks][0] = *(const uint32_t*)(Ql + (size_t)qrow*32 + kc);
            qAl[ks][1] = *(const uint32_t*)(Ql + (size_t)(qrow+8)*32 + kc);
            qAl[ks][2] = *(const uint32_t*)(Ql + (size_t)qrow*32 + kc + 8);
            qAl[ks][3] = *(const uint32_t*)(Ql + (size_t)(qrow+8)*32 + kc + 8);
        }
    }
    if (t < 64) { rowm[t] = -1e30f; rowl[t] = 0.f; }

    float O[16][4];
    #pragma unroll
    for (int i = 0; i < 16; i++)
        #pragma unroll
        for (int j = 0; j < 4; j++) O[i][j] = 0.f;

    // stage issuer: tile kt -> buffer st (V + K hi/lo)
    auto issue = [&](int kt, int st) {
        __half* Vd = Vs0 + st*256*VT_ST;
        const __half* Vsrc = Vt + (size_t)kt*256*VT_ST;
        // V: 256 rows x 64 halves = 2048 x 16B; 8 chunks/thread
        #pragma unroll
        for (int r = 0; r < 8; r++) {
            int i = t + r*256;
            int c = i >> 3, seg = i & 7;
            cpa16(Vd + c*VT_ST + seg*8, Vsrc + c*VT_ST + seg*8);
        }
        // K hi/lo: 64 rows x 32 halves each = 2x256 x 16B; 2 chunks/thread
        #pragma unroll
        for (int r = 0; r < 2; r++) {
            int i = t + r*256;
            int arr = i >> 8, row = (i >> 2) & 63, seg = i & 3;
            __half* Kd = (arr ? Kl0 : Kh0) + st*64*KK_ST;
            const __half* Ks = (arr ? Klg : Khg) + (size_t)(kt*64 + row)*32 + seg*8;
            cpa16(Kd + row*KK_ST + seg*8, Ks);
        }
    };

    issue(0, 0); cpa_commit();
    __syncthreads();   // rowm/rowl init visible

    for (int kt = 0; kt < 64; kt++) {
        if (kt + 1 < 64) issue(kt + 1, (kt + 1) & 1);
        cpa_commit();
        cpa_wait<1>();
        __syncthreads();
        int st = kt & 1;
        const __half* Khs = Kh0 + st*64*KK_ST;
        const __half* Kls = Kl0 + st*64*KK_ST;
        const __half* Vss = Vs0 + st*256*VT_ST;

        // QK logits (3-pass split fp16), K frags from smem
        float qacc[4][4];
        #pragma unroll
        for (int i = 0; i < 4; i++)
            #pragma unroll
            for (int j = 0; j < 4; j++) qacc[i][j] = 0.f;
        #pragma unroll
        for (int nf = 0; nf < 4; nf++) {
            int key = 32*wh + 8*nf + g;          // local key in tile
            #pragma unroll
            for (int ks = 0; ks < 2; ks++) {
                int kc = ks*16 + 2*tq;
                uint32_t Bh[2], Bl[2];
                Bh[0] = *(const uint32_t*)(Khs + key*KK_ST + kc);
                Bh[1] = *(const uint32_t*)(Khs + key*KK_ST + kc + 8);
                Bl[0] = *(const uint32_t*)(Kls + key*KK_ST + kc);
                Bl[1] = *(const uint32_t*)(Kls + key*KK_ST + kc + 8);
                mma_f16(qacc[nf], qAh[ks], Bh);
                mma_f16(qacc[nf], qAh[ks], Bl);
                mma_f16(qacc[nf], qAl[ks], Bh);
            }
        }
        {
            int pr = 16*wq + g;
            #pragma unroll
            for (int nf = 0; nf < 4; nf++) {
                int pc = 32*wh + 8*nf + 2*tq;
                Ps[pr*VT_ST + pc]       = qacc[nf][0];
                Ps[pr*VT_ST + pc + 1]   = qacc[nf][1];
                Ps[(pr+8)*VT_ST + pc]   = qacc[nf][2];
                Ps[(pr+8)*VT_ST + pc+1] = qacc[nf][3];
            }
        }
        __syncthreads();
        // online softmax: 4 threads/row
        {
            int r = t >> 2, sg = t & 3;
            const float* pr = Ps + r*VT_ST + sg*16;
            float mx = -1e30f;
            #pragma unroll
            for (int j = 0; j < 16; j++) mx = fmaxf(mx, pr[j]);
            mx = fmaxf(mx, __shfl_xor_sync(0xffffffffu, mx, 1));
            mx = fmaxf(mx, __shfl_xor_sync(0xffffffffu, mx, 2));
            float mold = rowm[r];
            float mnew = fmaxf(mold, mx);
            float s = 0.f;
            __half* pb = Pb + r*VT_ST + sg*16;
            #pragma unroll
            for (int j = 0; j < 16; j++) {
                float e = __expf(pr[j] - mnew);
                s += e;
                pb[j] = __float2half_rn(e);
            }
            s += __shfl_xor_sync(0xffffffffu, s, 1);
            s += __shfl_xor_sync(0xffffffffu, s, 2);
            if (sg == 0) {
                float alpha = __expf(mold - mnew);
                rowm[r] = mnew;
                rowl[r] = rowl[r]*alpha + s;
                rowa[r] = alpha;
            }
        }
        __syncthreads();
        // PV: O = O*alpha + P @ V'  (fp16, ldmatrix frags)
        {
            float al0 = rowa[16*wq + g];
            float al1 = rowa[16*wq + g + 8];
            #pragma unroll
            for (int nf = 0; nf < 16; nf++) {
                O[nf][0] *= al0; O[nf][1] *= al0;
                O[nf][2] *= al1; O[nf][3] *= al1;
            }
            #pragma unroll
            for (int ks = 0; ks < 4; ks++) {
                uint32_t pA[4];
                {
                    int row = 16*wq + l7 + lb3*8;
                    int col = 16*ks + lb4*8;
                    ldsm_x4(pA, Pb + row*VT_ST + col);
                }
                #pragma unroll
                for (int nfp = 0; nfp < 8; nfp++) {
                    int row = 128*wh + 16*nfp + l7 + lb4*8;   // ch
                    int col = 16*ks + lb3*8;                  // key
                    uint32_t Bf[4];
                    ldsm_x4(Bf, Vss + row*VT_ST + col);
                    mma_f16(O[2*nfp    ], pA, &Bf[0]);
                    mma_f16(O[2*nfp + 1], pA, &Bf[2]);
                }
            }
        }
        __syncthreads();
    }
    // epilogue: gamma * O/l + x  (raw-reshape flat indexing)
    {
        float gm = gamma[0];
        int row0 = q0 + 16*wq + g;
        float inv0 = 1.f / rowl[16*wq + g];
        float inv1 = 1.f / rowl[16*wq + g + 8];
        #pragma unroll
        for (int nf = 0; nf < 16; nf++) {
            int ch = 128*wh + 8*nf + 2*tq;
            size_t i0 = (size_t)b*CHW + (size_t)row0*256 + ch;
            size_t i1 = (size_t)b*CHW + (size_t)(row0+8)*256 + ch;
            out[i0]   = gm*O[nf][0]*inv0 + x[i0];
            out[i0+1] = gm*O[nf][1]*inv0 + x[i0+1];
            out[i1]   = gm*O[nf][2]*inv1 + x[i1];
            out[i1+1] = gm*O[nf][3]*inv1 + x[i1+1];
        }
    }
}

// ---------------- launch ----------------
extern "C" void kernel_launch(void* const* d_in, const int* in_sizes, int n_in,
                              void* d_out, int out_size) {
    const float* x     = (const float*)d_in[0];
    const float* w_off = (const float*)d_in[1];
    const float* b_off = (const float*)d_in[2];
    const float* wq    = (const float*)d_in[3];
    const float* bq    = (const float*)d_in[4];
    const float* wk    = (const float*)d_in[5];
    const float* bk    = (const float*)d_in[6];
    const float* wv    = (const float*)d_in[7];
    const float* bv    = (const float*)d_in[8];
    const float* gamma = (const float*)d_in[9];
    float* out = (float*)d_out;

    prep_wv_kernel<<<(CC*CK)/(256*4), 256>>>(wv);
    off_conv_kernel<<<dim3(16, 18, BB), 256>>>(x, w_off, b_off);
    sample_kernel<<<dim3((BB*9*HW)/256, 4), 256>>>(x);
    qk_gemm_kernel<<<dim3(64, BB), 256>>>(wq, bq, wk, bk);
    v_gemm_kernel<<<dim3(4, 32, BB), 256>>>(wv, bv);

    cudaFuncSetAttribute(attn_kernel, cudaFuncAttributeMaxDynamicSharedMemorySize,
                         SMEM_BYTES);
    attn_kernel<<<dim3(64, BB), 256, SMEM_BYTES>>>(x, gamma, out);
}